// round 14
// baseline (speedup 1.0000x reference)
#include <cuda_runtime.h>
#include <cuda_fp16.h>
#include <cstdint>

// -------------------- problem constants --------------------
#define B_SZ 4096
#define I_SZ 1024
#define H_SZ 2048
#define NSTEPS 5
#define DT_C 0.1f

// -------------------- GEMM tiling (frozen R4/fp16 body) --------------------
#define BM 128
#define BN 256
#define BK 32                 // 32 halves per k-tile = 64B rows
#define NSTAGE 4
#define THREADS 256

#define SA_BYTES (BM * 64)                    // 8192
#define SB_BYTES (BN * 64)                    // 16384
#define STAGE_BYTES (SA_BYTES + SB_BYTES)     // 24576
#define PIPE_BYTES (NSTAGE * STAGE_BYTES)     // 98304
#define STASH_LD   264                        // halves per stash row (pad 8)
#define STASH_BYTES (BM * STASH_LD * 2)       // 67584
#define SMEM_INV   PIPE_BYTES
#define SMEM_FUSED (PIPE_BYTES + STASH_BYTES) // 165888

// -------------------- scratch --------------------
__device__ __half g_C1h[B_SZ * H_SZ];
__device__ __half g_C2h[B_SZ * H_SZ];
__device__ __half g_h16A[B_SZ * H_SZ];
__device__ __half g_h16B[B_SZ * H_SZ];
__device__ __half g_x16  [B_SZ * I_SZ];
__device__ __half g_Wrec16[H_SZ * H_SZ];
__device__ __half g_tauh16[H_SZ * H_SZ];
__device__ __half g_Win16 [H_SZ * I_SZ];
__device__ __half g_taux16[H_SZ * I_SZ];

// -------------------- PTX helpers --------------------
__device__ __forceinline__ void cp16(uint32_t smem, const void* g) {
    asm volatile("cp.async.cg.shared.global [%0], [%1], 16;" :: "r"(smem), "l"(g) : "memory");
}
__device__ __forceinline__ void cp_commit() {
    asm volatile("cp.async.commit_group;" ::: "memory");
}
template <int N>
__device__ __forceinline__ void cp_wait() {
    asm volatile("cp.async.wait_group %0;" :: "n"(N) : "memory");
}
__device__ __forceinline__ void ldsm4(uint32_t* r, uint32_t a) {
    asm volatile("ldmatrix.sync.aligned.m8n8.x4.shared.b16 {%0,%1,%2,%3}, [%4];"
                 : "=r"(r[0]), "=r"(r[1]), "=r"(r[2]), "=r"(r[3]) : "r"(a));
}
__device__ __forceinline__ void mma_f16(float* d, const uint32_t* a, const uint32_t* b) {
    asm volatile(
        "mma.sync.aligned.m16n8k16.row.col.f32.f16.f16.f32 "
        "{%0,%1,%2,%3}, {%4,%5,%6,%7}, {%8,%9}, {%0,%1,%2,%3};"
        : "+f"(d[0]), "+f"(d[1]), "+f"(d[2]), "+f"(d[3])
        : "r"(a[0]), "r"(a[1]), "r"(a[2]), "r"(a[3]), "r"(b[0]), "r"(b[1]));
}
__device__ __forceinline__ uint32_t swadr(uint32_t base, int r, int g) {
    const int c = g ^ (r & 3) ^ ((r >> 2) & 1);
    return base + (uint32_t)(r * 64 + c * 16);
}

// -------------------- fused fp32 -> fp16 convert --------------------
struct CvtJob { const float* s; __half* d; int rows, cols, sld, dld; };
struct CvtJobs { CvtJob j[6]; };

__global__ void cvt_all_kernel(CvtJobs J)
{
    const CvtJob job = J.j[blockIdx.y];
    const int per_row = job.cols >> 3;
    const long total = (long)job.rows * per_row;
    for (long i = (long)blockIdx.x * blockDim.x + threadIdx.x; i < total;
         i += (long)gridDim.x * blockDim.x) {
        const int r = (int)(i / per_row);
        const int c = (int)(i % per_row) << 3;
        const float4 a = *(const float4*)(job.s + (long)r * job.sld + c);
        const float4 b = *(const float4*)(job.s + (long)r * job.sld + c + 4);
        __half2 h0 = __float22half2_rn(make_float2(a.x, a.y));
        __half2 h1 = __float22half2_rn(make_float2(a.z, a.w));
        __half2 h2 = __float22half2_rn(make_float2(b.x, b.y));
        __half2 h3 = __float22half2_rn(make_float2(b.z, b.w));
        uint4 u;
        u.x = *(uint32_t*)&h0; u.y = *(uint32_t*)&h1;
        u.z = *(uint32_t*)&h2; u.w = *(uint32_t*)&h3;
        *(uint4*)(job.d + (long)r * job.dld + c) = u;
    }
}

// ===================== invariant dual-B GEMM (one k-loop) ===================
// grid (16, 32): half = blockIdx.x>>3. C_half = x @ B_half^T + bias (fp16 out)
// lda = ldb = I_SZ for all operands; K = I_SZ.
__global__ void __launch_bounds__(THREADS, 1)
gemm_inv_f16(const __half* __restrict__ A,
             const __half* __restrict__ B0, __half* __restrict__ C0,
             const float* __restrict__ bias0,
             const __half* __restrict__ B1, __half* __restrict__ C1,
             const float* __restrict__ bias1)
{
    extern __shared__ __align__(1024) char smem[];
    const uint32_t sb = (uint32_t)__cvta_generic_to_shared(smem);

    const int tid  = threadIdx.x;
    const int lane = tid & 31;
    const int wid  = tid >> 5;
    const int wm   = (wid >> 2) * 64;
    const int wn   = (wid & 3) * 64;

    const int half_ = blockIdx.x >> 3;
    const int nblk  = blockIdx.x & 7;
    const int m0 = blockIdx.y * BM;
    const int n0 = nblk * BN;

    const __half* Bw   = half_ ? B1 : B0;
    __half*       C    = half_ ? C1 : C0;
    const float*  bias = half_ ? bias1 : bias0;

    const int lr = tid >> 2;
    const int lg = tid & 3;
    const __half* gA = A  + (long)(m0 + lr) * I_SZ + lg * 8;
    const __half* gB = Bw + (long)(n0 + lr) * I_SZ + lg * 8;
    const long str64 = (long)64 * I_SZ;

    const int arow = (lane & 7) + ((lane >> 3) & 1) * 8;
    const int agof = (lane >> 4);
    const int brow = (lane & 7) + ((lane >> 4) & 1) * 8;
    const int bgof = (lane >> 3) & 1;

    float acc[4][8][4];
#pragma unroll
    for (int mt = 0; mt < 4; mt++)
#pragma unroll
        for (int nt = 0; nt < 8; nt++)
#pragma unroll
            for (int r = 0; r < 4; r++) acc[mt][nt][r] = 0.f;

    const int nK = I_SZ / BK;

    auto load_stage = [&](int s, int kt) {
        const uint32_t sA = sb + s * STAGE_BYTES;
        const uint32_t sB = sA + SA_BYTES;
        const int koff = kt * BK;
        cp16(swadr(sA, lr,       lg), gA + koff);
        cp16(swadr(sA, lr + 64,  lg), gA + koff + str64);
        cp16(swadr(sB, lr,       lg), gB + koff);
        cp16(swadr(sB, lr + 64,  lg), gB + koff + str64);
        cp16(swadr(sB, lr + 128, lg), gB + koff + 2 * str64);
        cp16(swadr(sB, lr + 192, lg), gB + koff + 3 * str64);
    };

#pragma unroll
    for (int s = 0; s < NSTAGE - 1; s++) { load_stage(s, s); cp_commit(); }

    for (int kt = 0; kt < nK; kt++) {
        cp_wait<NSTAGE - 2>();
        __syncthreads();
        const int kload = kt + NSTAGE - 1;
        if (kload < nK) load_stage(kload & (NSTAGE - 1), kload);
        cp_commit();

        const uint32_t sA = sb + (kt & (NSTAGE - 1)) * STAGE_BYTES;
        const uint32_t sB = sA + SA_BYTES;
#pragma unroll
        for (int ks = 0; ks < 2; ks++) {
            uint32_t af[4][4], bf[4][4];
#pragma unroll
            for (int mt = 0; mt < 4; mt++)
                ldsm4(af[mt], swadr(sA, wm + mt * 16 + arow, 2 * ks + agof));
#pragma unroll
            for (int p = 0; p < 4; p++)
                ldsm4(bf[p], swadr(sB, wn + p * 16 + brow, 2 * ks + bgof));
#pragma unroll
            for (int mt = 0; mt < 4; mt++)
#pragma unroll
                for (int p = 0; p < 4; p++) {
                    mma_f16(acc[mt][2 * p],     af[mt], &bf[p][0]);
                    mma_f16(acc[mt][2 * p + 1], af[mt], &bf[p][2]);
                }
        }
    }

    const int grp = lane >> 2;
    const int tig = lane & 3;
#pragma unroll
    for (int mt = 0; mt < 4; mt++) {
        const int row0 = m0 + wm + mt * 16 + grp;
#pragma unroll
        for (int nt = 0; nt < 8; nt++) {
            const int col = n0 + wn + nt * 8 + 2 * tig;
            const float b0 = __ldg(bias + col), b1 = __ldg(bias + col + 1);
            __half2 p0 = __floats2half2_rn(acc[mt][nt][0] + b0, acc[mt][nt][1] + b1);
            __half2 p1 = __floats2half2_rn(acc[mt][nt][2] + b0, acc[mt][nt][3] + b1);
            *(__half2*)(C + (long)row0 * H_SZ + col)       = p0;
            *(__half2*)(C + (long)(row0 + 8) * H_SZ + col) = p1;
        }
    }
}

// ===================== fused dual-GEMM + liquid step ========================
// grid (8, 32): each CTA owns tile (m0, n0) of [4096, 2048].
// loop1: G1 = h@Btau^T -> stash (fp16, smem). loop2: G2 = h@Brec^T (fp32 acc).
// epilogue: liquid update, write hnext (+ fp32 h/tau on last step).
__global__ void __launch_bounds__(THREADS, 1)
gemm_liquid_f16(const __half* __restrict__ hcur,
                const __half* __restrict__ Btau,
                const __half* __restrict__ Brec,
                const __half* __restrict__ C1,
                const __half* __restrict__ C2,
                const float* __restrict__ tau_base,
                __half* __restrict__ hnext,
                float* __restrict__ h_out,
                float* __restrict__ tau_out)
{
    extern __shared__ __align__(1024) char smem[];
    const uint32_t sb = (uint32_t)__cvta_generic_to_shared(smem);
    __half* stash = (__half*)(smem + PIPE_BYTES);

    const int tid  = threadIdx.x;
    const int lane = tid & 31;
    const int wid  = tid >> 5;
    const int wm   = (wid >> 2) * 64;
    const int wn   = (wid & 3) * 64;

    const int m0 = blockIdx.y * BM;
    const int n0 = blockIdx.x * BN;

    const int lr = tid >> 2;
    const int lg = tid & 3;
    const __half* gA = hcur + (long)(m0 + lr) * H_SZ + lg * 8;
    const long str64 = (long)64 * H_SZ;

    const int arow = (lane & 7) + ((lane >> 3) & 1) * 8;
    const int agof = (lane >> 4);
    const int brow = (lane & 7) + ((lane >> 4) & 1) * 8;
    const int bgof = (lane >> 3) & 1;
    const int grp = lane >> 2;
    const int tig = lane & 3;

    float acc[4][8][4];
    const int nK = H_SZ / BK;

    auto zero_acc = [&]() {
#pragma unroll
        for (int mt = 0; mt < 4; mt++)
#pragma unroll
            for (int nt = 0; nt < 8; nt++)
#pragma unroll
                for (int r = 0; r < 4; r++) acc[mt][nt][r] = 0.f;
    };

    auto run_kloop = [&](const __half* Bmat) {
        const __half* gB = Bmat + (long)(n0 + lr) * H_SZ + lg * 8;
        auto load_stage = [&](int s, int kt) {
            const uint32_t sA = sb + s * STAGE_BYTES;
            const uint32_t sB = sA + SA_BYTES;
            const int koff = kt * BK;
            cp16(swadr(sA, lr,       lg), gA + koff);
            cp16(swadr(sA, lr + 64,  lg), gA + koff + str64);
            cp16(swadr(sB, lr,       lg), gB + koff);
            cp16(swadr(sB, lr + 64,  lg), gB + koff + str64);
            cp16(swadr(sB, lr + 128, lg), gB + koff + 2 * str64);
            cp16(swadr(sB, lr + 192, lg), gB + koff + 3 * str64);
        };
#pragma unroll
        for (int s = 0; s < NSTAGE - 1; s++) { load_stage(s, s); cp_commit(); }

        for (int kt = 0; kt < nK; kt++) {
            cp_wait<NSTAGE - 2>();
            __syncthreads();
            const int kload = kt + NSTAGE - 1;
            if (kload < nK) load_stage(kload & (NSTAGE - 1), kload);
            cp_commit();

            const uint32_t sA = sb + (kt & (NSTAGE - 1)) * STAGE_BYTES;
            const uint32_t sB = sA + SA_BYTES;
#pragma unroll
            for (int ks = 0; ks < 2; ks++) {
                uint32_t af[4][4], bf[4][4];
#pragma unroll
                for (int mt = 0; mt < 4; mt++)
                    ldsm4(af[mt], swadr(sA, wm + mt * 16 + arow, 2 * ks + agof));
#pragma unroll
                for (int p = 0; p < 4; p++)
                    ldsm4(bf[p], swadr(sB, wn + p * 16 + brow, 2 * ks + bgof));
#pragma unroll
                for (int mt = 0; mt < 4; mt++)
#pragma unroll
                    for (int p = 0; p < 4; p++) {
                        mma_f16(acc[mt][2 * p],     af[mt], &bf[p][0]);
                        mma_f16(acc[mt][2 * p + 1], af[mt], &bf[p][2]);
                    }
            }
        }
    };

    // ---- loop 1: G1 = h @ Btau^T ----
    zero_acc();
    run_kloop(Btau);

    // stash G1 tile (fp16, same rounding as previous global G1h path)
#pragma unroll
    for (int mt = 0; mt < 4; mt++) {
        const int rl = wm + mt * 16 + grp;
#pragma unroll
        for (int nt = 0; nt < 8; nt++) {
            const int cl = wn + nt * 8 + 2 * tig;
            __half2 p0 = __floats2half2_rn(acc[mt][nt][0], acc[mt][nt][1]);
            __half2 p1 = __floats2half2_rn(acc[mt][nt][2], acc[mt][nt][3]);
            *(__half2*)(stash + rl * STASH_LD + cl)       = p0;
            *(__half2*)(stash + (rl + 8) * STASH_LD + cl) = p1;
        }
    }
    __syncthreads();   // stash complete; pipeline smem free for loop 2

    // ---- loop 2: G2 = h @ Brec^T (stays fp32 in acc) ----
    zero_acc();
    run_kloop(Brec);

    // ---- liquid epilogue ----
#pragma unroll
    for (int mt = 0; mt < 4; mt++) {
        const int rl0 = wm + mt * 16 + grp;
#pragma unroll
        for (int nt = 0; nt < 8; nt++) {
            const int cl  = wn + nt * 8 + 2 * tig;
            const int col = n0 + cl;
            const float2 tb = *(const float2*)(tau_base + col);
#pragma unroll
            for (int rr = 0; rr < 2; rr++) {
                const int rl = rl0 + rr * 8;
                const long off = (long)(m0 + rl) * H_SZ + col;
                const float2 g1v = __half22float2(*(const __half2*)(stash + rl * STASH_LD + cl));
                const float2 c1v = __half22float2(*(const __half2*)(C1 + off));
                const float2 c2v = __half22float2(*(const __half2*)(C2 + off));
                const float2 hv  = __half22float2(*(const __half2*)(hcur + off));
                float2 hn, tv;
                {
                    const float g2  = acc[mt][nt][2 * rr];
                    const float tl  = c2v.x + g1v.x;
                    const float sg  = 1.f / (1.f + expf(-tl));
                    const float tau = tb.x * (0.5f + sg);
                    const float act = tanhf(g2 + c1v.x);
                    hn.x = hv.x + DT_C * (act - hv.x) / tau;
                    tv.x = tau;
                }
                {
                    const float g2  = acc[mt][nt][2 * rr + 1];
                    const float tl  = c2v.y + g1v.y;
                    const float sg  = 1.f / (1.f + expf(-tl));
                    const float tau = tb.y * (0.5f + sg);
                    const float act = tanhf(g2 + c1v.y);
                    hn.y = hv.y + DT_C * (act - hv.y) / tau;
                    tv.y = tau;
                }
                *(__half2*)(hnext + off) = __float22half2_rn(hn);
                if (h_out)   *(float2*)(h_out + off)   = hn;
                if (tau_out) *(float2*)(tau_out + off) = tv;
            }
        }
    }
}

// -------------------- launcher --------------------
extern "C" void kernel_launch(void* const* d_in, const int* in_sizes, int n_in,
                              void* d_out, int out_size)
{
    (void)in_sizes; (void)n_in; (void)out_size;

    const float* x           = (const float*)d_in[0];
    const float* hidden      = (const float*)d_in[1];
    const float* W_rec       = (const float*)d_in[2];
    const float* W_in_w      = (const float*)d_in[3];
    const float* W_in_b      = (const float*)d_in[4];
    const float* tau_base    = (const float*)d_in[5];
    const float* tau_adapt_w = (const float*)d_in[6];
    const float* tau_adapt_b = (const float*)d_in[7];

    float* out_h   = (float*)d_out;
    float* out_tau = out_h + (long)B_SZ * H_SZ;

    __half *C1h, *C2h, *h16A, *h16B, *x16, *Wrec16, *tauh16, *Win16, *taux16;
    cudaGetSymbolAddress((void**)&C1h,    g_C1h);
    cudaGetSymbolAddress((void**)&C2h,    g_C2h);
    cudaGetSymbolAddress((void**)&h16A,   g_h16A);
    cudaGetSymbolAddress((void**)&h16B,   g_h16B);
    cudaGetSymbolAddress((void**)&x16,    g_x16);
    cudaGetSymbolAddress((void**)&Wrec16, g_Wrec16);
    cudaGetSymbolAddress((void**)&tauh16, g_tauh16);
    cudaGetSymbolAddress((void**)&Win16,  g_Win16);
    cudaGetSymbolAddress((void**)&taux16, g_taux16);

    cudaFuncSetAttribute(gemm_inv_f16,    cudaFuncAttributeMaxDynamicSharedMemorySize, SMEM_INV);
    cudaFuncSetAttribute(gemm_liquid_f16, cudaFuncAttributeMaxDynamicSharedMemorySize, SMEM_FUSED);

    const int ldtau = I_SZ + H_SZ;     // 3072

    // ---- one fused conversion launch ----
    CvtJobs J;
    J.j[0] = {x,                  x16,    B_SZ, I_SZ, I_SZ,  I_SZ};
    J.j[1] = {hidden,             h16A,   B_SZ, H_SZ, H_SZ,  H_SZ};
    J.j[2] = {W_rec,              Wrec16, H_SZ, H_SZ, H_SZ,  H_SZ};
    J.j[3] = {tau_adapt_w + I_SZ, tauh16, H_SZ, H_SZ, ldtau, H_SZ};
    J.j[4] = {W_in_w,             Win16,  H_SZ, I_SZ, I_SZ,  I_SZ};
    J.j[5] = {tau_adapt_w,        taux16, H_SZ, I_SZ, ldtau, I_SZ};
    cvt_all_kernel<<<dim3(128, 6), 256>>>(J);

    // ---- invariant GEMMs: C1 = x@W_in^T + b, C2 = x@tau_x^T + tb ----
    gemm_inv_f16<<<dim3(16, B_SZ / BM), THREADS, SMEM_INV>>>(
        x16, Win16, C1h, W_in_b, taux16, C2h, tau_adapt_b);

    // ---- 5 fused GEMM+liquid steps (h16 ping-pong) ----
    for (int s = 0; s < NSTEPS; s++) {
        const __half* hc = (s & 1) ? h16B : h16A;
        __half*       hn = (s & 1) ? h16A : h16B;
        float* ho = (s == NSTEPS - 1) ? out_h   : nullptr;
        float* to = (s == NSTEPS - 1) ? out_tau : nullptr;
        gemm_liquid_f16<<<dim3(H_SZ / BN, B_SZ / BM), THREADS, SMEM_FUSED>>>(
            hc, tauh16, Wrec16, C1h, C2h, tau_base, hn, ho, to);
    }
}

// round 15
// speedup vs baseline: 1.3004x; 1.3004x over previous
#include <cuda_runtime.h>
#include <cuda_fp16.h>
#include <cstdint>

// -------------------- problem constants --------------------
#define B_SZ 4096
#define I_SZ 1024
#define H_SZ 2048
#define NSTEPS 5
#define DT_C 0.1f

// -------------------- GEMM tiling (fp16, 128-thread CTA, 2 CTAs/SM) -------
#define BM 128
#define BN 128
#define BK 32                 // 32 halves per k-tile = 64B rows
#define NSTAGE 4
#define THREADS 128

#define SA_BYTES (BM * 64)                    // 8192
#define SB_BYTES (BN * 64)                    // 8192
#define STAGE_BYTES (SA_BYTES + SB_BYTES)     // 16384
#define SMEM_TOTAL (NSTAGE * STAGE_BYTES)     // 65536 (x2 CTAs = 128K <= 228K)

// -------------------- scratch --------------------
__device__ __half g_C1h[B_SZ * H_SZ];
__device__ __half g_C2h[B_SZ * H_SZ];
__device__ __half g_G1h[B_SZ * H_SZ];
__device__ __half g_G2h[B_SZ * H_SZ];
__device__ __half g_h16  [B_SZ * H_SZ];
__device__ __half g_x16  [B_SZ * I_SZ];
__device__ __half g_Wrec16[H_SZ * H_SZ];
__device__ __half g_tauh16[H_SZ * H_SZ];
__device__ __half g_Win16 [H_SZ * I_SZ];
__device__ __half g_taux16[H_SZ * I_SZ];

// -------------------- PTX helpers --------------------
__device__ __forceinline__ void cp16(uint32_t smem, const void* g) {
    asm volatile("cp.async.cg.shared.global [%0], [%1], 16;" :: "r"(smem), "l"(g) : "memory");
}
__device__ __forceinline__ void cp_commit() {
    asm volatile("cp.async.commit_group;" ::: "memory");
}
template <int N>
__device__ __forceinline__ void cp_wait() {
    asm volatile("cp.async.wait_group %0;" :: "n"(N) : "memory");
}
__device__ __forceinline__ void ldsm4(uint32_t* r, uint32_t a) {
    asm volatile("ldmatrix.sync.aligned.m8n8.x4.shared.b16 {%0,%1,%2,%3}, [%4];"
                 : "=r"(r[0]), "=r"(r[1]), "=r"(r[2]), "=r"(r[3]) : "r"(a));
}
__device__ __forceinline__ void mma_f16(float* d, const uint32_t* a, const uint32_t* b) {
    asm volatile(
        "mma.sync.aligned.m16n8k16.row.col.f32.f16.f16.f32 "
        "{%0,%1,%2,%3}, {%4,%5,%6,%7}, {%8,%9}, {%0,%1,%2,%3};"
        : "+f"(d[0]), "+f"(d[1]), "+f"(d[2]), "+f"(d[3])
        : "r"(a[0]), "r"(a[1]), "r"(a[2]), "r"(a[3]), "r"(b[0]), "r"(b[1]));
}
__device__ __forceinline__ uint32_t swadr(uint32_t base, int r, int g) {
    const int c = g ^ (r & 3) ^ ((r >> 2) & 1);
    return base + (uint32_t)(r * 64 + c * 16);
}
__device__ __forceinline__ float4 h4_to_f4(uint2 u) {
    const __half2 a = *(__half2*)&u.x;
    const __half2 b = *(__half2*)&u.y;
    const float2 fa = __half22float2(a);
    const float2 fb = __half22float2(b);
    return make_float4(fa.x, fa.y, fb.x, fb.y);
}

// -------------------- fused fp32 -> fp16 convert --------------------
struct CvtJob { const float* s; __half* d; int rows, cols, sld, dld; };
struct CvtJobs { CvtJob j[6]; };

__global__ void cvt_all_kernel(CvtJobs J)
{
    const CvtJob job = J.j[blockIdx.y];
    const int per_row = job.cols >> 3;
    const long total = (long)job.rows * per_row;
    for (long i = (long)blockIdx.x * blockDim.x + threadIdx.x; i < total;
         i += (long)gridDim.x * blockDim.x) {
        const int r = (int)(i / per_row);
        const int c = (int)(i % per_row) << 3;
        const float4 a = *(const float4*)(job.s + (long)r * job.sld + c);
        const float4 b = *(const float4*)(job.s + (long)r * job.sld + c + 4);
        __half2 h0 = __float22half2_rn(make_float2(a.x, a.y));
        __half2 h1 = __float22half2_rn(make_float2(a.z, a.w));
        __half2 h2 = __float22half2_rn(make_float2(b.x, b.y));
        __half2 h3 = __float22half2_rn(make_float2(b.z, b.w));
        uint4 u;
        u.x = *(uint32_t*)&h0; u.y = *(uint32_t*)&h1;
        u.z = *(uint32_t*)&h2; u.w = *(uint32_t*)&h3;
        *(uint4*)(job.d + (long)r * job.dld + c) = u;
    }
}

// -------------------- dual-B fp16 GEMM, job-table, 2 CTAs/SM ---------------
// Each job: two GEMMs (B0->C0, B1->C1) over the full [M, H_SZ] output.
// grid.x = 32 (one job) or 64 (two jobs, job = blockIdx.x >> 5).
// Within a job: half = (x>>4)&1, nblk = x&15 (BN=128 -> 16 n-blocks).
struct GemmJob {
    const __half *A; int lda;
    const __half *B0; int ldb0; __half *C0; const float *bias0;
    const __half *B1; int ldb1; __half *C1; const float *bias1;
    int K;
};

__global__ void __launch_bounds__(THREADS, 2)
gemm_dual_f16(GemmJob j0, GemmJob j1)
{
    extern __shared__ __align__(1024) char smem[];
    const uint32_t sb = (uint32_t)__cvta_generic_to_shared(smem);

    const int tid  = threadIdx.x;
    const int lane = tid & 31;
    const int wid  = tid >> 5;           // 0..3
    const int wm   = (wid >> 1) * 64;    // 0 / 64
    const int wn   = (wid & 1) * 64;     // 0 / 64

    const GemmJob jb = (blockIdx.x >> 5) ? j1 : j0;
    const int x5    = blockIdx.x & 31;
    const int half_ = x5 >> 4;
    const int nblk  = x5 & 15;
    const int m0 = blockIdx.y * BM;
    const int n0 = nblk * BN;

    const __half* A    = jb.A;
    const int     lda  = jb.lda;
    const __half* Bw   = half_ ? jb.B1 : jb.B0;
    const int     ldb  = half_ ? jb.ldb1 : jb.ldb0;
    __half*       C    = half_ ? jb.C1 : jb.C0;
    const float*  bias = half_ ? jb.bias1 : jb.bias0;
    const int     K    = jb.K;

    // ---- loader coordinates: row lr (0..63, plus +64), chunks lc/lc+1 ----
    const int lr = tid >> 1;
    const int lc = (tid & 1) * 2;
    const __half* gA = A  + (long)(m0 + lr) * lda + lc * 8;
    const __half* gB = Bw + (long)(n0 + lr) * ldb + lc * 8;
    const long strideA64 = (long)64 * lda;
    const long strideB64 = (long)64 * ldb;

    const int arow = (lane & 7) + ((lane >> 3) & 1) * 8;
    const int agof = (lane >> 4);
    const int brow = (lane & 7) + ((lane >> 4) & 1) * 8;
    const int bgof = (lane >> 3) & 1;

    float acc[4][8][4];
#pragma unroll
    for (int mt = 0; mt < 4; mt++)
#pragma unroll
        for (int nt = 0; nt < 8; nt++)
#pragma unroll
            for (int r = 0; r < 4; r++) acc[mt][nt][r] = 0.f;

    const int nK = K / BK;

    // ---- stage loader (8 cp.async per thread) ----
    auto load_stage = [&](int s, int kt) {
        const uint32_t sA = sb + s * STAGE_BYTES;
        const uint32_t sB = sA + SA_BYTES;
        const int koff = kt * BK;
        cp16(swadr(sA, lr,      lc),     gA + koff);
        cp16(swadr(sA, lr,      lc + 1), gA + koff + 8);
        cp16(swadr(sA, lr + 64, lc),     gA + koff + strideA64);
        cp16(swadr(sA, lr + 64, lc + 1), gA + koff + strideA64 + 8);
        cp16(swadr(sB, lr,      lc),     gB + koff);
        cp16(swadr(sB, lr,      lc + 1), gB + koff + 8);
        cp16(swadr(sB, lr + 64, lc),     gB + koff + strideB64);
        cp16(swadr(sB, lr + 64, lc + 1), gB + koff + strideB64 + 8);
    };

#pragma unroll
    for (int s = 0; s < NSTAGE - 1; s++) {
        load_stage(s, s);
        cp_commit();
    }

    for (int kt = 0; kt < nK; kt++) {
        cp_wait<NSTAGE - 2>();
        __syncthreads();

        const int kload = kt + NSTAGE - 1;
        if (kload < nK) load_stage(kload & (NSTAGE - 1), kload);
        cp_commit();

        const uint32_t sA = sb + (kt & (NSTAGE - 1)) * STAGE_BYTES;
        const uint32_t sB = sA + SA_BYTES;

#pragma unroll
        for (int ks = 0; ks < 2; ks++) {
            uint32_t af[4][4], bf[4][4];
#pragma unroll
            for (int mt = 0; mt < 4; mt++)
                ldsm4(af[mt], swadr(sA, wm + mt * 16 + arow, 2 * ks + agof));
#pragma unroll
            for (int p = 0; p < 4; p++)
                ldsm4(bf[p], swadr(sB, wn + p * 16 + brow, 2 * ks + bgof));
#pragma unroll
            for (int mt = 0; mt < 4; mt++)
#pragma unroll
                for (int p = 0; p < 4; p++) {
                    mma_f16(acc[mt][2 * p],     af[mt], &bf[p][0]);
                    mma_f16(acc[mt][2 * p + 1], af[mt], &bf[p][2]);
                }
        }
    }

    // ---- epilogue: fp16 stores ----
    const int grp = lane >> 2;
    const int tig = lane & 3;
#pragma unroll
    for (int mt = 0; mt < 4; mt++) {
        const int row0 = m0 + wm + mt * 16 + grp;
#pragma unroll
        for (int nt = 0; nt < 8; nt++) {
            const int col = n0 + wn + nt * 8 + 2 * tig;
            float b0 = 0.f, b1 = 0.f;
            if (bias) { b0 = __ldg(bias + col); b1 = __ldg(bias + col + 1); }
            __half2 p0 = __floats2half2_rn(acc[mt][nt][0] + b0, acc[mt][nt][1] + b1);
            __half2 p1 = __floats2half2_rn(acc[mt][nt][2] + b0, acc[mt][nt][3] + b1);
            *(__half2*)(C + (long)row0 * H_SZ + col)       = p0;
            *(__half2*)(C + (long)(row0 + 8) * H_SZ + col) = p1;
        }
    }
}

// -------------------- elementwise liquid step (fp16 state, in place) -------
__global__ void __launch_bounds__(256)
liquid_step_kernel(__half* __restrict__ h16,
                   const __half* __restrict__ G1,
                   const __half* __restrict__ G2,
                   const __half* __restrict__ C1,
                   const __half* __restrict__ C2,
                   const float* __restrict__ tau_base,
                   float* __restrict__ h_out,
                   float* __restrict__ tau_out)
{
    const int idx = (blockIdx.x * 256 + threadIdx.x) * 4;
    const int j = idx & (H_SZ - 1);

    float4 g1 = h4_to_f4(*(const uint2*)(G1 + idx));
    float4 g2 = h4_to_f4(*(const uint2*)(G2 + idx));
    float4 c1 = h4_to_f4(*(const uint2*)(C1 + idx));
    float4 c2 = h4_to_f4(*(const uint2*)(C2 + idx));
    float4 hv = h4_to_f4(*(const uint2*)(h16 + idx));
    float4 tb = *(const float4*)(tau_base + j);

    float4 hn, tv;
#define ONE_LANE(f)                                                        \
    {                                                                      \
        float tl  = c2.f + g1.f;                                           \
        float sg  = 1.f / (1.f + expf(-tl));                               \
        float tau = tb.f * (0.5f + sg);                                    \
        float act = tanhf(g2.f + c1.f);                                    \
        hn.f = hv.f + DT_C * (act - hv.f) / tau;                           \
        tv.f = tau;                                                        \
    }
    ONE_LANE(x) ONE_LANE(y) ONE_LANE(z) ONE_LANE(w)
#undef ONE_LANE

    __half2 p0 = __float22half2_rn(make_float2(hn.x, hn.y));
    __half2 p1 = __float22half2_rn(make_float2(hn.z, hn.w));
    uint2 u; u.x = *(uint32_t*)&p0; u.y = *(uint32_t*)&p1;
    *(uint2*)(h16 + idx) = u;

    if (h_out)   *(float4*)(h_out + idx)   = hn;
    if (tau_out) *(float4*)(tau_out + idx) = tv;
}

// -------------------- launcher --------------------
extern "C" void kernel_launch(void* const* d_in, const int* in_sizes, int n_in,
                              void* d_out, int out_size)
{
    (void)in_sizes; (void)n_in; (void)out_size;

    const float* x           = (const float*)d_in[0];
    const float* hidden      = (const float*)d_in[1];
    const float* W_rec       = (const float*)d_in[2];
    const float* W_in_w      = (const float*)d_in[3];
    const float* W_in_b      = (const float*)d_in[4];
    const float* tau_base    = (const float*)d_in[5];
    const float* tau_adapt_w = (const float*)d_in[6];
    const float* tau_adapt_b = (const float*)d_in[7];

    float* out_h   = (float*)d_out;
    float* out_tau = out_h + (long)B_SZ * H_SZ;

    __half *C1h, *C2h, *G1h, *G2h, *x16, *h16, *Wrec16, *tauh16, *Win16, *taux16;
    cudaGetSymbolAddress((void**)&C1h,    g_C1h);
    cudaGetSymbolAddress((void**)&C2h,    g_C2h);
    cudaGetSymbolAddress((void**)&G1h,    g_G1h);
    cudaGetSymbolAddress((void**)&G2h,    g_G2h);
    cudaGetSymbolAddress((void**)&x16,    g_x16);
    cudaGetSymbolAddress((void**)&h16,    g_h16);
    cudaGetSymbolAddress((void**)&Wrec16, g_Wrec16);
    cudaGetSymbolAddress((void**)&tauh16, g_tauh16);
    cudaGetSymbolAddress((void**)&Win16,  g_Win16);
    cudaGetSymbolAddress((void**)&taux16, g_taux16);

    cudaFuncSetAttribute(gemm_dual_f16, cudaFuncAttributeMaxDynamicSharedMemorySize, SMEM_TOTAL);

    const int ldtau = I_SZ + H_SZ;     // 3072

    // ---- one fused conversion launch ----
    CvtJobs J;
    J.j[0] = {x,                  x16,    B_SZ, I_SZ, I_SZ,  I_SZ};
    J.j[1] = {hidden,             h16,    B_SZ, H_SZ, H_SZ,  H_SZ};
    J.j[2] = {W_rec,              Wrec16, H_SZ, H_SZ, H_SZ,  H_SZ};
    J.j[3] = {tau_adapt_w + I_SZ, tauh16, H_SZ, H_SZ, ldtau, H_SZ};
    J.j[4] = {W_in_w,             Win16,  H_SZ, I_SZ, I_SZ,  I_SZ};
    J.j[5] = {tau_adapt_w,        taux16, H_SZ, I_SZ, ldtau, I_SZ};
    cvt_all_kernel<<<dim3(128, 6), 256>>>(J);

    // ---- merged launch: invariant GEMMs (job0) + step-0 GEMMs (job1) ----
    GemmJob inv  = { x16, I_SZ,
                     Win16,  I_SZ, C1h, W_in_b,
                     taux16, I_SZ, C2h, tau_adapt_b,
                     I_SZ };
    GemmJob loop = { h16, H_SZ,
                     tauh16, H_SZ, G1h, nullptr,
                     Wrec16, H_SZ, G2h, nullptr,
                     H_SZ };

    gemm_dual_f16<<<dim3(64, B_SZ / BM), THREADS, SMEM_TOTAL>>>(inv, loop);

    const int n_ew = (B_SZ * H_SZ) / 4 / 256;
    for (int s = 0; s < NSTEPS; s++) {
        if (s > 0)
            gemm_dual_f16<<<dim3(32, B_SZ / BM), THREADS, SMEM_TOTAL>>>(loop, loop);

        float* ho = (s == NSTEPS - 1) ? out_h   : nullptr;
        float* to = (s == NSTEPS - 1) ? out_tau : nullptr;
        liquid_step_kernel<<<n_ew, 256>>>(h16, G1h, G2h, C1h, C2h, tau_base, ho, to);
    }
}